// round 17
// baseline (speedup 1.0000x reference)
#include <cuda_runtime.h>
#include <cuda_fp16.h>
#include <stdint.h>

#define IN_W 256
#define IN_HW 65536
#define OUT_W 254
#define OUT_HW (254 * 254)

#define ROWP 528                 // 66 pos * 8 half2-words per ring row
#define RING_WORDS (16 * ROWP)   // 16-row rolling fp16 ring
#define WF_WORDS (9 * 128)
#define SMEM_BYTES ((RING_WORDS + WF_WORDS + 16) * 4)   // 38,464 B -> 4 CTAs/SM

__device__ __forceinline__ void mma_f16(float c[4], uint32_t a0, uint32_t a1,
                                        uint32_t a2, uint32_t a3,
                                        uint32_t b0, uint32_t b1) {
    asm("mma.sync.aligned.m16n8k16.row.col.f32.f16.f16.f32 "
        "{%0,%1,%2,%3}, {%4,%5,%6,%7}, {%8,%9}, {%0,%1,%2,%3};"
        : "+f"(c[0]), "+f"(c[1]), "+f"(c[2]), "+f"(c[3])
        : "r"(a0), "r"(a1), "r"(a2), "r"(a3), "r"(b0), "r"(b1));
}
__device__ __forceinline__ float mish_f(float v) {
    if (v > 30.0f) return v;
    float e  = __expf(v);
    float t  = 1.0f + e;
    float t2 = t * t;
    return v * __fdividef(t2 - 1.0f, t2 + 1.0f);
}

// load one (row,pos,part) item (8 fp32), convert, store 16B into ring slot
// (4g+row)&15.  Values live only inside this macro -> no regs across mainloop.
#define LDCVT_ITEM(row_, pos_, part_, g)                                        \
    do {                                                                        \
        int gy = Y0 + 4 * (g) + (row_); if (gy > 255) gy = 255;                 \
        int gx = X0 + (pos_);           if (gx > 255) gx = 255;                 \
        const float* p_ = xn + gy * IN_W + gx;                                  \
        float v_[8];                                                            \
        _Pragma("unroll")                                                       \
        for (int w_ = 0; w_ < 4; w_++) {                                        \
            int wq_ = 4 * (part_) + w_;                                         \
            int lo_ = ((wq_ & 1) << 3) + ((wq_ >> 1) << 1);                     \
            v_[2 * w_]     = p_[(size_t)lo_ * IN_HW];                           \
            v_[2 * w_ + 1] = p_[(size_t)(lo_ + 1) * IN_HW];                     \
        }                                                                       \
        uint4 q_;                                                               \
        uint32_t* qw_ = (uint32_t*)&q_;                                         \
        _Pragma("unroll")                                                       \
        for (int w_ = 0; w_ < 4; w_++) {                                        \
            __half2 h_ = __floats2half2_rn(v_[2 * w_], v_[2 * w_ + 1]);         \
            qw_[w_] = *(uint32_t*)&h_;                                          \
        }                                                                       \
        *(uint4*)(ring + ((4 * (g) + (row_)) & 15) * ROWP                       \
                  + (pos_) * 8 + (part_) * 4) = q_;                             \
    } while (0)

__global__ __launch_bounds__(256, 4)
void conv_tc_kernel(const float* __restrict__ x,
                    const float* __restrict__ w,
                    const float* __restrict__ bias,
                    float* __restrict__ y)
{
    extern __shared__ uint32_t sm[];
    uint32_t* ring = sm;                     // fp16 ring [slot16][pos66][8 words]
    uint32_t* Wf   = sm + RING_WORDS;
    float*    bsm  = (float*)(sm + RING_WORDS + WF_WORDS);

    const int tid  = threadIdx.x;
    const int wid  = tid >> 5;
    const int lane = tid & 31;
    const int lm   = lane >> 2;
    const int lk   = lane & 3;
    const int X0   = blockIdx.x * 64;
    const int Y0   = blockIdx.y * 16;
    const int n    = blockIdx.z;

    if (tid < 16) bsm[tid] = bias[tid];

    // ---- weight A fragments (m16n8k16): Wf[t*128 + ln*4 + word]
    for (int i = tid; i < WF_WORDS; i += 256) {
        int word = i & 3;
        int ln   = (i >> 2) & 31;
        int t    = i >> 7;                   // ky*3+kx
        int ky   = t / 3, kx = t % 3;
        int co   = (ln >> 2) + (word & 1) * 8;
        int cilo = 2 * (ln & 3) + (word >> 1) * 8;
        __half2 h = __floats2half2_rn(w[(co * 16 + cilo) * 9 + ky * 3 + kx],
                                      w[(co * 16 + cilo + 1) * 9 + ky * 3 + kx]);
        Wf[i] = *(uint32_t*)&h;
    }

    // ---- loader slots: 4 rows/group = 512 body items (2/thread) + 16 halo
    int srow[2], spart[2], spos[2];
    #pragma unroll
    for (int s = 0; s < 2; s++) {
        int j = tid + 256 * s;
        spart[s] = j & 1;
        spos[s]  = (j >> 1) & 63;
        srow[s]  = j >> 7;                   // s=0: rows 0-1, s=1: rows 2-3
    }
    int hrow = 0, hpart = 0, hpos = 0;
    if (tid < 16) {
        hrow  = tid >> 2;
        hpos  = 64 + ((tid >> 1) & 1);
        hpart = tid & 1;
    }
    const float* xn = x + (size_t)n * 16 * IN_HW;

    // ---- prologue: groups 0,1
    #pragma unroll
    for (int g = 0; g < 2; g++) {
        LDCVT_ITEM(srow[0], spos[0], spart[0], g);
        LDCVT_ITEM(srow[1], spos[1], spart[1], g);
        if (tid < 16) LDCVT_ITEM(hrow, hpos, hpart, g);
    }
    __syncthreads();

    const int rr = wid >> 1;             // warp's row within subtile (0..3)
    const int q  = (wid & 1) * 32;       // warp's 32-pos quarter

    #pragma unroll 1
    for (int s4 = 0; s4 < 4; s4++) {
        // ---- load+convert+store group s4+2 at phase top (slots disjoint from
        // this phase's reads; visibility to phase s4+1 via end-of-phase barrier)
        if (s4 < 3) {
            const int gld  = s4 + 2;
            const int rlim = (gld == 4) ? 2 : 4;   // group 4 = rows 16,17 only
            #pragma unroll
            for (int s = 0; s < 2; s++)
                if (srow[s] < rlim)
                    LDCVT_ITEM(srow[s], spos[s], spart[s], gld);
            if (tid < 16 && hrow < rlim)
                LDCVT_ITEM(hrow, hpos, hpart, gld);
        }

        // ---- 36 MMAs on ring groups s4, s4+1
        float c[4][4];
        #pragma unroll
        for (int j = 0; j < 4; j++)
            #pragma unroll
            for (int e = 0; e < 4; e++) c[j][e] = 0.f;

        #pragma unroll
        for (int ky = 0; ky < 3; ky++) {
            const uint4* wf = (const uint4*)(Wf + ky * 3 * 128) + lane;
            uint4 A0 = wf[0];
            uint4 A1 = wf[32];
            uint4 A2 = wf[64];
            int slot = (4 * s4 + rr + ky) & 15;
            const uint32_t* bb = ring + slot * ROWP + (q + lm) * 8 + 2 * lk;
            #pragma unroll
            for (int kx = 0; kx < 3; kx++) {
                uint2 b[4];
                #pragma unroll
                for (int j = 0; j < 4; j++)
                    b[j] = *(const uint2*)(bb + kx * 8 + j * 64);
                uint4 Ax = (kx == 0) ? A0 : (kx == 1) ? A1 : A2;
                #pragma unroll
                for (int j = 0; j < 4; j++)
                    mma_f16(c[j], Ax.x, Ax.y, Ax.z, Ax.w, b[j].x, b[j].y);
            }
        }

        // ---- epilogue
        const int yo = Y0 + 4 * s4 + rr;
        if (yo < OUT_W) {
            float b0f = bsm[lm] - 0.7f;
            float b1f = bsm[lm + 8] - 0.7f;
            float* y0 = y + ((size_t)n * 16 + lm) * OUT_HW + (size_t)yo * OUT_W;
            float* y1 = y0 + 8 * OUT_HW;
            #pragma unroll
            for (int j = 0; j < 4; j++) {
                int xo = X0 + q + 8 * j + 2 * lk;   // even; float2 pair fully in/out
                if (xo < OUT_W) {
                    float2 v0, v1;
                    v0.x = mish_f(c[j][0] + b0f);
                    v0.y = mish_f(c[j][1] + b0f);
                    v1.x = mish_f(c[j][2] + b1f);
                    v1.y = mish_f(c[j][3] + b1f);
                    *(float2*)(y0 + xo) = v0;
                    *(float2*)(y1 + xo) = v1;
                }
            }
        }
        __syncthreads();   // orders this phase's STS before phase s4+1 reads
    }
}

extern "C" void kernel_launch(void* const* d_in, const int* in_sizes, int n_in,
                              void* d_out, int out_size)
{
    const float* x  = (const float*)d_in[0];
    const float* w  = (const float*)d_in[1];
    const float* b  = (const float*)d_in[2];
    float* y = (float*)d_out;

    cudaFuncSetAttribute(conv_tc_kernel,
                         cudaFuncAttributeMaxDynamicSharedMemorySize, SMEM_BYTES);

    int N = in_sizes[0] / (16 * IN_HW);                 // 32
    dim3 grid(4, 16, N);                                // 2048 CTAs
    conv_tc_kernel<<<grid, 256, SMEM_BYTES>>>(x, w, b, y);
}